// round 12
// baseline (speedup 1.0000x reference)
#include <cuda_runtime.h>
#include <cuda_fp16.h>
#include <math.h>
#include <stdint.h>

#define BSZ 8192
#define EMB 256
#define INV_T (1.0f/0.07f)
#define GAMMAC 0.1f
#define EPSC 1e-10f

#define SCALEF     20.609929155556625f   // (1/0.07) * log2(e)
#define INV_SCALEF 0.048520302639196164f // 1/SCALEF
#define SQ         254.0f                // int8 quant scale (|x| <= 0.5 assumed)
#define KQ         (SCALEF / (SQ * SQ))  // acc_int -> sim*SCALEF

// GEMM tiling: CTA 128x128, 8 warps (warp tile 32x64), K loaded fully into
// a 2-stage ring (KC=128 bytes/row per stage), 2 CTAs/SM.
#define BM 128
#define BN 128
#define KC 128
#define NROWT (BSZ / BN)      // 64 row-partial strips
#define NCOLT (BSZ / BM)      // 64 col-partial strips
#define STAGEB 32768          // bytes per stage: A 16K + B 16K

#define NLOSSBLK (2 * BSZ / 256)   // 64 loss blocks

// ---- device scratch (static allocation; no runtime allocs) ----
__device__ int8_t gA8[(size_t)BSZ * EMB];
__device__ int8_t gB8[(size_t)BSZ * EMB];
__device__ float g_rowPartE [(size_t)NROWT * BSZ];
__device__ float g_rowPartES[(size_t)NROWT * BSZ];
__device__ float g_colPartE [(size_t)NCOLT * BSZ];
__device__ float g_colPartES[(size_t)NCOLT * BSZ];
__device__ float g_diag[BSZ];
__device__ volatile float g_lossPart[NLOSSBLK];
__device__ unsigned g_lossTicket;            // zero-init; self-resets each launch

__device__ __forceinline__ float ex2(float x) {
    float y;
    asm("ex2.approx.f32 %0, %1;" : "=f"(y) : "f"(x));
    return y;
}

__device__ __forceinline__ void ldsm4(uint32_t r[4], uint32_t addr) {
    asm volatile("ldmatrix.sync.aligned.m8n8.x4.shared.b16 {%0,%1,%2,%3}, [%4];"
        : "=r"(r[0]), "=r"(r[1]), "=r"(r[2]), "=r"(r[3]) : "r"(addr));
}

// int8 IMMA: m16n8k32, s32 accumulate. 4096 MACs/instr (2x fp16 HMMA).
__device__ __forceinline__ void imma16832(int c[4], const uint32_t a[4],
                                          uint32_t b0, uint32_t b1) {
    asm volatile(
        "mma.sync.aligned.m16n8k32.row.col.s32.s8.s8.s32 "
        "{%0,%1,%2,%3}, {%4,%5,%6,%7}, {%8,%9}, {%0,%1,%2,%3};"
        : "+r"(c[0]), "+r"(c[1]), "+r"(c[2]), "+r"(c[3])
        : "r"(a[0]), "r"(a[1]), "r"(a[2]), "r"(a[3]), "r"(b0), "r"(b1));
}

__device__ __forceinline__ uint32_t smem_u32(const void* p) {
    uint32_t a;
    asm("{ .reg .u64 t; cvta.to.shared.u64 t, %1; cvt.u32.u64 %0, t; }" : "=r"(a) : "l"(p));
    return a;
}

__device__ __forceinline__ void cpasync16(uint32_t dst, const void* src) {
    asm volatile("cp.async.cg.shared.global [%0], [%1], 16;" :: "r"(dst), "l"(src));
}
#define CP_COMMIT() asm volatile("cp.async.commit_group;" ::: "memory")
#define CP_WAIT(n)  asm volatile("cp.async.wait_group %0;" :: "n"(n) : "memory")

// ---------------------------------------------------------------------------
// Kernel 0: single-pass prep. One warp per row: read img+txt rows once,
// compute exact fp32 diag dot, write both int8 rows (scale SQ, saturating).
// ---------------------------------------------------------------------------
__device__ __forceinline__ int q8(float x) {
    int v = __float2int_rn(x * SQ);
    return v < -127 ? -127 : (v > 127 ? 127 : v);
}

__global__ void __launch_bounds__(256) k_prep(
    const float* __restrict__ img, const float* __restrict__ txt)
{
    const int row  = blockIdx.x * 8 + (threadIdx.x >> 5);
    const int lane = threadIdx.x & 31;

    const float4* ap = reinterpret_cast<const float4*>(img + (size_t)row * EMB) + lane * 2;
    const float4* bp = reinterpret_cast<const float4*>(txt + (size_t)row * EMB) + lane * 2;
    float4 a0 = ap[0], a1 = ap[1];
    float4 b0 = bp[0], b1 = bp[1];

    float s = (a0.x*b0.x + a0.y*b0.y) + (a0.z*b0.z + a0.w*b0.w)
            + (a1.x*b1.x + a1.y*b1.y) + (a1.z*b1.z + a1.w*b1.w);
    #pragma unroll
    for (int o = 16; o; o >>= 1) s += __shfl_xor_sync(0xffffffffu, s, o);
    if (lane == 0) g_diag[row] = s;

    uint32_t pa0 = (q8(a0.x) & 0xFF) | ((q8(a0.y) & 0xFF) << 8)
                 | ((q8(a0.z) & 0xFF) << 16) | ((q8(a0.w) & 0xFF) << 24);
    uint32_t pa1 = (q8(a1.x) & 0xFF) | ((q8(a1.y) & 0xFF) << 8)
                 | ((q8(a1.z) & 0xFF) << 16) | ((q8(a1.w) & 0xFF) << 24);
    uint32_t pb0 = (q8(b0.x) & 0xFF) | ((q8(b0.y) & 0xFF) << 8)
                 | ((q8(b0.z) & 0xFF) << 16) | ((q8(b0.w) & 0xFF) << 24);
    uint32_t pb1 = (q8(b1.x) & 0xFF) | ((q8(b1.y) & 0xFF) << 8)
                 | ((q8(b1.z) & 0xFF) << 16) | ((q8(b1.w) & 0xFF) << 24);
    *reinterpret_cast<uint2*>(gA8 + (size_t)row * EMB + lane * 8) = make_uint2(pa0, pa1);
    *reinterpret_cast<uint2*>(gB8 + (size_t)row * EMB + lane * 8) = make_uint2(pb0, pb1);
}

// ---------------------------------------------------------------------------
// Kernel 1: fused int8 GEMM (s32 accum, exact) + exp2 + partial sums.
// CTA tile 128x128, 8 warps (warp tile 32x64), 2 stages hold ALL of K.
// ---------------------------------------------------------------------------
extern __shared__ char dsm[];

__global__ void __launch_bounds__(256, 2) k_gemm_fused()
{
    __shared__ float srowE[2][BM], srowES[2][BM];
    __shared__ float scolE[4][BN], scolES[4][BN];

    const int tid  = threadIdx.x;
    const int wid  = tid >> 5, lane = tid & 31;
    const int wm   = wid >> 1;          // 0..3 -> row offset wm*32
    const int wn   = wid & 1;           // 0..1 -> col offset wn*64
    const int kLane = lane & 3;
    const int bm   = blockIdx.y * BM, bn = blockIdx.x * BN;

    const uint32_t smemBase = smem_u32(dsm);

    int acc[2][8][4];
    #pragma unroll
    for (int mt = 0; mt < 2; mt++)
        #pragma unroll
        for (int nt = 0; nt < 8; nt++)
            #pragma unroll
            for (int q = 0; q < 4; q++) acc[mt][nt][q] = 0;

    // stage loader: A 128 rows x 128B (1024 16B-slots), B same
    {
        const int ldRow = tid >> 3, ldCh = tid & 7;
        #pragma unroll
        for (int c = 0; c < 2; c++) {           // chunk c -> stage c
            const int kt = c * KC;
            uint32_t sA = smemBase + c * STAGEB;
            uint32_t sB = sA + 16384;
            #pragma unroll
            for (int i = 0; i < 4; i++) {
                int row = ldRow + i * 32;
                uint32_t off = (row << 7) + ((ldCh ^ (row & 7)) << 4);
                cpasync16(sA + off, gA8 + (size_t)(bm + row) * EMB + kt + ldCh * 16);
                cpasync16(sB + off, gB8 + (size_t)(bn + row) * EMB + kt + ldCh * 16);
            }
            CP_COMMIT();
        }
    }

    #pragma unroll
    for (int c = 0; c < 2; c++) {
        if (c == 0) CP_WAIT(1); else CP_WAIT(0);
        __syncthreads();
        const uint32_t aBase = smemBase + c * STAGEB;
        const uint32_t bBase = aBase + 16384;

        #pragma unroll
        for (int ks = 0; ks < 4; ks++) {        // 4 k32-steps per 128B chunk
            uint32_t a[2][4];
            #pragma unroll
            for (int mt = 0; mt < 2; mt++) {
                int row = wm * 32 + mt * 16 + (lane & 15);
                int ch  = ks * 2 + (lane >> 4);
                ldsm4(a[mt], aBase + (row << 7) + ((ch ^ (row & 7)) << 4));
            }
            uint32_t bb[4][4];
            #pragma unroll
            for (int p = 0; p < 4; p++) {
                int row = wn * 64 + p * 16 + ((lane >> 4) << 3) + (lane & 7);
                int ch  = ks * 2 + ((lane >> 3) & 1);
                ldsm4(bb[p], bBase + (row << 7) + ((ch ^ (row & 7)) << 4));
            }
            #pragma unroll
            for (int mt = 0; mt < 2; mt++)
                #pragma unroll
                for (int p = 0; p < 4; p++) {
                    imma16832(acc[mt][2 * p],     a[mt], bb[p][0], bb[p][1]);
                    imma16832(acc[mt][2 * p + 1], a[mt], bb[p][2], bb[p][3]);
                }
        }
    }

    // ---- epilogue: sv = acc*KQ (= sim*SCALEF); E = exp2(sv); partial sums ----
    float rE[2][2], rES[2][2];
    #pragma unroll
    for (int mt = 0; mt < 2; mt++)
        #pragma unroll
        for (int h = 0; h < 2; h++) { rE[mt][h] = 0.f; rES[mt][h] = 0.f; }

    #pragma unroll
    for (int nt = 0; nt < 8; nt++) {
        float e[2][4], sv[2][4];
        #pragma unroll
        for (int mt = 0; mt < 2; mt++)
            #pragma unroll
            for (int q = 0; q < 4; q++) {
                sv[mt][q] = (float)acc[mt][nt][q] * KQ;
                e[mt][q] = ex2(sv[mt][q]);
            }
        float cE0 = 0.f, cE1 = 0.f, cES0 = 0.f, cES1 = 0.f;
        #pragma unroll
        for (int mt = 0; mt < 2; mt++) {
            rE [mt][0] += e[mt][0] + e[mt][1];
            rES[mt][0] += e[mt][0]*sv[mt][0] + e[mt][1]*sv[mt][1];
            rE [mt][1] += e[mt][2] + e[mt][3];
            rES[mt][1] += e[mt][2]*sv[mt][2] + e[mt][3]*sv[mt][3];
            cE0  += e[mt][0] + e[mt][2];
            cE1  += e[mt][1] + e[mt][3];
            cES0 += e[mt][0]*sv[mt][0] + e[mt][2]*sv[mt][2];
            cES1 += e[mt][1]*sv[mt][1] + e[mt][3]*sv[mt][3];
        }
        #pragma unroll
        for (int o = 4; o <= 16; o <<= 1) {
            cE0  += __shfl_xor_sync(0xffffffffu, cE0,  o);
            cE1  += __shfl_xor_sync(0xffffffffu, cE1,  o);
            cES0 += __shfl_xor_sync(0xffffffffu, cES0, o);
            cES1 += __shfl_xor_sync(0xffffffffu, cES1, o);
        }
        if (lane < 4) {
            int cl = wn * 64 + nt * 8 + 2 * lane;
            scolE [wm][cl]     = cE0;
            scolE [wm][cl + 1] = cE1;
            scolES[wm][cl]     = cES0;
            scolES[wm][cl + 1] = cES1;
        }
    }
    #pragma unroll
    for (int mt = 0; mt < 2; mt++)
        #pragma unroll
        for (int h = 0; h < 2; h++)
            #pragma unroll
            for (int o = 1; o <= 2; o <<= 1) {
                rE [mt][h] += __shfl_xor_sync(0xffffffffu, rE [mt][h], o);
                rES[mt][h] += __shfl_xor_sync(0xffffffffu, rES[mt][h], o);
            }
    if (kLane == 0) {
        #pragma unroll
        for (int mt = 0; mt < 2; mt++)
            #pragma unroll
            for (int h = 0; h < 2; h++) {
                int rl = wm * 32 + mt * 16 + h * 8 + (lane >> 2);
                srowE [wn][rl] = rE [mt][h];
                srowES[wn][rl] = rES[mt][h];
            }
    }
    __syncthreads();

    if (tid < BM) {      // row partials (128 rows)
        size_t idx = (size_t)blockIdx.x * BSZ + bm + tid;
        g_rowPartE [idx] = srowE [0][tid] + srowE [1][tid];
        g_rowPartES[idx] = (srowES[0][tid] + srowES[1][tid]) * INV_SCALEF;
    } else {             // col partials (128 cols)
        int t = tid - BM;
        size_t idx = (size_t)blockIdx.y * BSZ + bn + t;
        g_colPartE [idx] = (scolE [0][t] + scolE [1][t]) + (scolE [2][t] + scolE [3][t]);
        g_colPartES[idx] = ((scolES[0][t] + scolES[1][t]) + (scolES[2][t] + scolES[3][t]))
                           * INV_SCALEF;
    }
}

// ---------------------------------------------------------------------------
// Kernel 2: losses + per-block partial sums; the LAST block to finish (atomic
// ticket) reduces all partials in fixed order and writes the final scalar.
// ---------------------------------------------------------------------------
__global__ void __launch_bounds__(256) k_loss(
    const float* __restrict__ s_I, const float* __restrict__ s_T,
    const int* __restrict__ iid, const int* __restrict__ tid_,
    float* __restrict__ out)
{
    int t = blockIdx.x * 256 + threadIdx.x;     // 0 .. 2*BSZ-1
    bool isRow = t < BSZ;
    int i = isRow ? t : t - BSZ;
    const float* pE  = isRow ? g_rowPartE  : g_colPartE;
    const float* pES = isRow ? g_rowPartES : g_colPartES;
    float sumE = 0.f, sumES = 0.f;
    #pragma unroll 8
    for (int k = 0; k < 64; k++) {              // NROWT == NCOLT == 64
        sumE  += pE [(size_t)k * BSZ + i];
        sumES += pES[(size_t)k * BSZ + i];
    }
    float d = g_diag[i];
    float f = __expf(-d * INV_T);
    float Se  = f * sumE;
    float Sed = f * (sumES - d * sumE);
    const float invBm1 = 1.0f / (float)(BSZ - 1);
    float gv = Se * invBm1;
    float sOld = isRow ? s_I[iid[i]] : s_T[tid_[i]];
    float sNew = (1.0f - GAMMAC) * sOld + GAMMAC * gv;
    float loss = (Sed * invBm1) / (sNew + EPSC);

    __shared__ float sl[256];
    __shared__ bool sLast;
    sl[threadIdx.x] = loss;
    __syncthreads();
    #pragma unroll
    for (int o = 128; o; o >>= 1) {
        if (threadIdx.x < o) sl[threadIdx.x] += sl[threadIdx.x + o];
        __syncthreads();
    }
    if (threadIdx.x == 0) {
        g_lossPart[blockIdx.x] = sl[0];
        __threadfence();
        unsigned done = atomicAdd(&g_lossTicket, 1u);
        sLast = (done == NLOSSBLK - 1);
    }
    __syncthreads();
    if (sLast) {
        __threadfence();
        float v = (threadIdx.x < NLOSSBLK) ? g_lossPart[threadIdx.x] : 0.f;
        sl[threadIdx.x] = v;
        __syncthreads();
        #pragma unroll
        for (int o = 128; o; o >>= 1) {
            if (threadIdx.x < o) sl[threadIdx.x] += sl[threadIdx.x + o];
            __syncthreads();
        }
        if (threadIdx.x == 0) {
            out[0] = sl[0] / (float)BSZ;
            g_lossTicket = 0u;            // reset for next graph replay
        }
    }
}

// ---------------------------------------------------------------------------
extern "C" void kernel_launch(void* const* d_in, const int* in_sizes, int n_in,
                              void* d_out, int out_size)
{
    const float* img = (const float*)d_in[0];
    const float* txt = (const float*)d_in[1];
    const float* s_I = (const float*)d_in[4];
    const float* s_T = (const float*)d_in[5];
    const int*   iid = (const int*)d_in[6];
    const int*   tid = (const int*)d_in[7];

    static bool attrDone = false;
    if (!attrDone) {
        cudaFuncSetAttribute(k_gemm_fused,
                             cudaFuncAttributeMaxDynamicSharedMemorySize, 2 * STAGEB);
        attrDone = true;
    }

    k_prep<<<BSZ / 8, 256>>>(img, txt);          // warp per row, single pass
    dim3 g(BSZ / BN, BSZ / BM);                  // 64 x 64 tiles
    k_gemm_fused<<<g, 256, 2 * STAGEB>>>();
    k_loss<<<NLOSSBLK, 256>>>(s_I, s_T, iid, tid, (float*)d_out);
}

// round 13
// speedup vs baseline: 2.8424x; 2.8424x over previous
#include <cuda_runtime.h>
#include <cuda_fp16.h>
#include <math.h>
#include <stdint.h>

#define BSZ 8192
#define EMB 256
#define INV_T (1.0f/0.07f)
#define GAMMAC 0.1f
#define EPSC 1e-10f

// A is pre-scaled by SCALE so acc = sim * SCALE and exp(sim/T) = exp2(acc).
#define SCALEF     20.609929155556625f   // (1/0.07) * log2(e)
#define INV_SCALEF 0.048520302639196164f // 1/SCALEF
#define SVOFF      5.0f                  // epilogue log2-shift (fp16 range safety)

// GEMM tiling: CTA 256x128, 8 warps (warp tile 64x64), KC=64, 2-stage ring,
// 2 CTAs/SM for cross-CTA prologue/epilogue overlap.
#define BM 256
#define BN 128
#define KC 64
#define NROWT (BSZ / BN)      // 64 row-partial strips
#define NCOLT (BSZ / BM)      // 32 col-partial strips
#define STAGEB 49152          // bytes per stage: A 32K + B 16K

#define NLOSSBLK (2 * BSZ / 256)   // 64 loss blocks

// ---- device scratch (static allocation; no runtime allocs) ----
__device__ __half gA16[(size_t)BSZ * EMB];   // fp16, pre-scaled by SCALEF
__device__ __half gB16[(size_t)BSZ * EMB];   // fp16
__device__ float g_rowPartE [(size_t)NROWT * BSZ];
__device__ float g_rowPartES[(size_t)NROWT * BSZ];
__device__ float g_colPartE [(size_t)NCOLT * BSZ];
__device__ float g_colPartES[(size_t)NCOLT * BSZ];
__device__ float g_diag[BSZ];
__device__ volatile float g_lossPart[NLOSSBLK];
__device__ unsigned g_lossTicket;            // zero-init; self-resets each launch

__device__ __forceinline__ __half2 h2ex2(__half2 x) {
    __half2 y;
    asm("ex2.approx.f16x2 %0, %1;"
        : "=r"(*reinterpret_cast<uint32_t*>(&y))
        : "r"(*reinterpret_cast<const uint32_t*>(&x)));
    return y;
}

__device__ __forceinline__ __half2 shfl_xor_h2(__half2 v, int o) {
    uint32_t u = __shfl_xor_sync(0xffffffffu, *reinterpret_cast<uint32_t*>(&v), o);
    return *reinterpret_cast<__half2*>(&u);
}

__device__ __forceinline__ void ldsm4(uint32_t r[4], uint32_t addr) {
    asm volatile("ldmatrix.sync.aligned.m8n8.x4.shared.b16 {%0,%1,%2,%3}, [%4];"
        : "=r"(r[0]), "=r"(r[1]), "=r"(r[2]), "=r"(r[3]) : "r"(addr));
}

// fp16-accumulate MMA (halves acc regs -> enables 2 CTAs/SM).
__device__ __forceinline__ void mma16816h(uint32_t c[2], const uint32_t a[4],
                                          uint32_t b0, uint32_t b1) {
    asm volatile(
        "mma.sync.aligned.m16n8k16.row.col.f16.f16.f16.f16 "
        "{%0,%1}, {%2,%3,%4,%5}, {%6,%7}, {%0,%1};"
        : "+r"(c[0]), "+r"(c[1])
        : "r"(a[0]), "r"(a[1]), "r"(a[2]), "r"(a[3]), "r"(b0), "r"(b1));
}

__device__ __forceinline__ uint32_t smem_u32(const void* p) {
    uint32_t a;
    asm("{ .reg .u64 t; cvta.to.shared.u64 t, %1; cvt.u32.u64 %0, t; }" : "=r"(a) : "l"(p));
    return a;
}

__device__ __forceinline__ void cpasync16(uint32_t dst, const void* src) {
    asm volatile("cp.async.cg.shared.global [%0], [%1], 16;" :: "r"(dst), "l"(src));
}
#define CP_COMMIT() asm volatile("cp.async.commit_group;" ::: "memory")
#define CP_WAIT(n)  asm volatile("cp.async.wait_group %0;" :: "n"(n) : "memory")

// ---------------------------------------------------------------------------
// Kernel 0: single-pass prep. One warp per row: read img+txt rows once,
// compute exact fp32 diag dot, write both fp16 rows (A scaled by SCALEF).
// ---------------------------------------------------------------------------
__global__ void __launch_bounds__(256) k_prep(
    const float* __restrict__ img, const float* __restrict__ txt)
{
    const int row  = blockIdx.x * 8 + (threadIdx.x >> 5);
    const int lane = threadIdx.x & 31;

    const float4* ap = reinterpret_cast<const float4*>(img + (size_t)row * EMB) + lane * 2;
    const float4* bp = reinterpret_cast<const float4*>(txt + (size_t)row * EMB) + lane * 2;
    float4 a0 = ap[0], a1 = ap[1];
    float4 b0 = bp[0], b1 = bp[1];

    float s = (a0.x*b0.x + a0.y*b0.y) + (a0.z*b0.z + a0.w*b0.w)
            + (a1.x*b1.x + a1.y*b1.y) + (a1.z*b1.z + a1.w*b1.w);
    #pragma unroll
    for (int o = 16; o; o >>= 1) s += __shfl_xor_sync(0xffffffffu, s, o);
    if (lane == 0) g_diag[row] = s;

    __half2 ha0 = __floats2half2_rn(a0.x * SCALEF, a0.y * SCALEF);
    __half2 ha1 = __floats2half2_rn(a0.z * SCALEF, a0.w * SCALEF);
    __half2 ha2 = __floats2half2_rn(a1.x * SCALEF, a1.y * SCALEF);
    __half2 ha3 = __floats2half2_rn(a1.z * SCALEF, a1.w * SCALEF);
    __half2 hb0 = __floats2half2_rn(b0.x, b0.y);
    __half2 hb1 = __floats2half2_rn(b0.z, b0.w);
    __half2 hb2 = __floats2half2_rn(b1.x, b1.y);
    __half2 hb3 = __floats2half2_rn(b1.z, b1.w);
    uint4 oa, ob;
    oa.x = *reinterpret_cast<uint32_t*>(&ha0);
    oa.y = *reinterpret_cast<uint32_t*>(&ha1);
    oa.z = *reinterpret_cast<uint32_t*>(&ha2);
    oa.w = *reinterpret_cast<uint32_t*>(&ha3);
    ob.x = *reinterpret_cast<uint32_t*>(&hb0);
    ob.y = *reinterpret_cast<uint32_t*>(&hb1);
    ob.z = *reinterpret_cast<uint32_t*>(&hb2);
    ob.w = *reinterpret_cast<uint32_t*>(&hb3);
    *reinterpret_cast<uint4*>(gA16 + (size_t)row * EMB + lane * 8) = oa;
    *reinterpret_cast<uint4*>(gB16 + (size_t)row * EMB + lane * 8) = ob;
}

// ---------------------------------------------------------------------------
// Kernel 1: fused fp16 GEMM (fp16 accum) + fp16 exp2 epilogue + partial sums.
// CTA tile 256x128, 8 warps (warp tile 64x64), KC=64, 2-stage, 2 CTAs/SM.
// ---------------------------------------------------------------------------
extern __shared__ char dsm[];

__global__ void __launch_bounds__(256, 2) k_gemm_fused()
{
    __shared__ float srowE[2][BM], srowES[2][BM];
    __shared__ float scolE[4][BN], scolES[4][BN];

    const int tid  = threadIdx.x;
    const int wid  = tid >> 5, lane = tid & 31;
    const int wm   = wid >> 1;          // 0..3 -> row offset wm*64
    const int wn   = wid & 1;           // 0..1 -> col offset wn*64
    const int kLane = lane & 3;
    const int bm   = blockIdx.y * BM, bn = blockIdx.x * BN;

    const uint32_t smemBase = smem_u32(dsm);

    uint32_t acc[4][8][2];              // half2 accumulators
    #pragma unroll
    for (int mt = 0; mt < 4; mt++)
        #pragma unroll
        for (int nt = 0; nt < 8; nt++) { acc[mt][nt][0] = 0u; acc[mt][nt][1] = 0u; }

    auto load_stage = [&](int c, int stage) {
        const int kt = c * KC;
        uint32_t sA = smemBase + stage * STAGEB;
        uint32_t sB = sA + 32768;
        #pragma unroll
        for (int i = 0; i < 8; i++) {
            int slot = tid + i * 256;
            int row = slot >> 3, ch = slot & 7;
            uint32_t off = (row << 7) + ((ch ^ (row & 7)) << 4);
            cpasync16(sA + off, gA16 + (size_t)(bm + row) * EMB + kt + ch * 8);
        }
        #pragma unroll
        for (int i = 0; i < 4; i++) {
            int slot = tid + i * 256;
            int row = slot >> 3, ch = slot & 7;
            uint32_t off = (row << 7) + ((ch ^ (row & 7)) << 4);
            cpasync16(sB + off, gB16 + (size_t)(bn + row) * EMB + kt + ch * 8);
        }
        CP_COMMIT();
    };

    load_stage(0, 0);
    load_stage(1, 1);

    #pragma unroll
    for (int c = 0; c < EMB / KC; c++) {
        if (c < EMB / KC - 1) CP_WAIT(1); else CP_WAIT(0);
        __syncthreads();
        const uint32_t aBase = smemBase + (c & 1) * STAGEB;
        const uint32_t bBase = aBase + 32768;

        #pragma unroll
        for (int ks = 0; ks < 4; ks++) {
            uint32_t a[4][4];
            #pragma unroll
            for (int mt = 0; mt < 4; mt++) {
                int row = wm * 64 + mt * 16 + (lane & 15);
                int ch  = ks * 2 + (lane >> 4);
                ldsm4(a[mt], aBase + (row << 7) + ((ch ^ (row & 7)) << 4));
            }
            uint32_t bb[4][4];
            #pragma unroll
            for (int p = 0; p < 4; p++) {
                int row = wn * 64 + p * 16 + ((lane >> 4) << 3) + (lane & 7);
                int ch  = ks * 2 + ((lane >> 3) & 1);
                ldsm4(bb[p], bBase + (row << 7) + ((ch ^ (row & 7)) << 4));
            }
            #pragma unroll
            for (int mt = 0; mt < 4; mt++)
                #pragma unroll
                for (int p = 0; p < 4; p++) {
                    mma16816h(acc[mt][2 * p],     a[mt], bb[p][0], bb[p][1]);
                    mma16816h(acc[mt][2 * p + 1], a[mt], bb[p][2], bb[p][3]);
                }
        }
        // refill the stage just consumed (2-stage ring needs a post-read barrier)
        if (c + 2 < EMB / KC) {
            __syncthreads();
            load_stage(c + 2, c & 1);
        }
    }

    // ---- epilogue (all fp16): a' = acc - 5; E = exp2(a'); sums of E, E*a' ----
    const __half2 h5 = __floats2half2_rn(SVOFF, SVOFF);
    const __half2 hz = __floats2half2_rn(0.f, 0.f);
    __half2 rE2[4][2], rES2[4][2];      // [mt][row-half +0/+8]; lanes = cols c,c+1
    #pragma unroll
    for (int mt = 0; mt < 4; mt++)
        #pragma unroll
        for (int h = 0; h < 2; h++) { rE2[mt][h] = hz; rES2[mt][h] = hz; }

    #pragma unroll
    for (int nt = 0; nt < 8; nt++) {
        __half2 cE2 = hz, cES2 = hz;
        #pragma unroll
        for (int mt = 0; mt < 4; mt++) {
            __half2 a0 = __hsub2(*reinterpret_cast<__half2*>(&acc[mt][nt][0]), h5);
            __half2 a1 = __hsub2(*reinterpret_cast<__half2*>(&acc[mt][nt][1]), h5);
            __half2 e0 = h2ex2(a0);
            __half2 e1 = h2ex2(a1);
            rE2 [mt][0] = __hadd2(rE2[mt][0], e0);
            rE2 [mt][1] = __hadd2(rE2[mt][1], e1);
            rES2[mt][0] = __hfma2(e0, a0, rES2[mt][0]);
            rES2[mt][1] = __hfma2(e1, a1, rES2[mt][1]);
            cE2  = __hadd2(cE2, __hadd2(e0, e1));
            cES2 = __hfma2(e0, a0, __hfma2(e1, a1, cES2));
        }
        #pragma unroll
        for (int o = 4; o <= 16; o <<= 1) {
            cE2  = __hadd2(cE2,  shfl_xor_h2(cE2,  o));
            cES2 = __hadd2(cES2, shfl_xor_h2(cES2, o));
        }
        if (lane < 4) {
            float2 vE = __half22float2(cE2);
            float2 vS = __half22float2(cES2);
            int cl = wn * 64 + nt * 8 + 2 * lane;
            scolE [wm][cl]     = vE.x;
            scolE [wm][cl + 1] = vE.y;
            scolES[wm][cl]     = vS.x;
            scolES[wm][cl + 1] = vS.y;
        }
    }
    #pragma unroll
    for (int mt = 0; mt < 4; mt++)
        #pragma unroll
        for (int h = 0; h < 2; h++)
            #pragma unroll
            for (int o = 1; o <= 2; o <<= 1) {
                rE2 [mt][h] = __hadd2(rE2 [mt][h], shfl_xor_h2(rE2 [mt][h], o));
                rES2[mt][h] = __hadd2(rES2[mt][h], shfl_xor_h2(rES2[mt][h], o));
            }
    if (kLane == 0) {
        #pragma unroll
        for (int mt = 0; mt < 4; mt++)
            #pragma unroll
            for (int h = 0; h < 2; h++) {
                int rl = wm * 64 + mt * 16 + h * 8 + (lane >> 2);
                float2 v = __half22float2(rE2 [mt][h]);
                float2 w = __half22float2(rES2[mt][h]);
                srowE [wn][rl] = v.x + v.y;
                srowES[wn][rl] = w.x + w.y;
            }
    }
    __syncthreads();

    {   // row partials (256 rows); ES stays in shifted log2 units * INV_SCALEF
        size_t idx = (size_t)blockIdx.x * BSZ + bm + tid;
        g_rowPartE [idx] = srowE [0][tid] + srowE [1][tid];
        g_rowPartES[idx] = (srowES[0][tid] + srowES[1][tid]) * INV_SCALEF;
    }
    if (tid < BN) {   // col partials (128 cols)
        size_t idx = (size_t)blockIdx.y * BSZ + bn + tid;
        g_colPartE [idx] = (scolE [0][tid] + scolE [1][tid]) + (scolE [2][tid] + scolE [3][tid]);
        g_colPartES[idx] = ((scolES[0][tid] + scolES[1][tid]) + (scolES[2][tid] + scolES[3][tid]))
                           * INV_SCALEF;
    }
}

// ---------------------------------------------------------------------------
// Kernel 2: losses + per-block partial sums; the LAST block to finish (atomic
// ticket) reduces all partials in fixed order and writes the final scalar.
// Accounts for the epilogue's SVOFF shift: E*sv = E*sv_sh + SVOFF*E.
// ---------------------------------------------------------------------------
__global__ void __launch_bounds__(256) k_loss(
    const float* __restrict__ s_I, const float* __restrict__ s_T,
    const int* __restrict__ iid, const int* __restrict__ tid_,
    float* __restrict__ out)
{
    int t = blockIdx.x * 256 + threadIdx.x;     // 0 .. 2*BSZ-1
    bool isRow = t < BSZ;
    int i = isRow ? t : t - BSZ;
    int nStrips = isRow ? NROWT : NCOLT;
    const float* pE  = isRow ? g_rowPartE  : g_colPartE;
    const float* pES = isRow ? g_rowPartES : g_colPartES;
    float sumE = 0.f, sumES = 0.f;
    #pragma unroll 8
    for (int k = 0; k < nStrips; k++) {
        sumE  += pE [(size_t)k * BSZ + i];
        sumES += pES[(size_t)k * BSZ + i];
    }
    sumES += (SVOFF * INV_SCALEF) * sumE;       // undo epilogue log2 shift
    float d = g_diag[i];
    float f = __expf(-d * INV_T);
    float Se  = f * sumE;
    float Sed = f * (sumES - d * sumE);
    const float invBm1 = 1.0f / (float)(BSZ - 1);
    float gv = Se * invBm1;
    float sOld = isRow ? s_I[iid[i]] : s_T[tid_[i]];
    float sNew = (1.0f - GAMMAC) * sOld + GAMMAC * gv;
    float loss = (Sed * invBm1) / (sNew + EPSC);

    __shared__ float sl[256];
    __shared__ bool sLast;
    sl[threadIdx.x] = loss;
    __syncthreads();
    #pragma unroll
    for (int o = 128; o; o >>= 1) {
        if (threadIdx.x < o) sl[threadIdx.x] += sl[threadIdx.x + o];
        __syncthreads();
    }
    if (threadIdx.x == 0) {
        g_lossPart[blockIdx.x] = sl[0];
        __threadfence();
        unsigned done = atomicAdd(&g_lossTicket, 1u);
        sLast = (done == NLOSSBLK - 1);
    }
    __syncthreads();
    if (sLast) {
        __threadfence();
        float v = (threadIdx.x < NLOSSBLK) ? g_lossPart[threadIdx.x] : 0.f;
        sl[threadIdx.x] = v;
        __syncthreads();
        #pragma unroll
        for (int o = 128; o; o >>= 1) {
            if (threadIdx.x < o) sl[threadIdx.x] += sl[threadIdx.x + o];
            __syncthreads();
        }
        if (threadIdx.x == 0) {
            out[0] = sl[0] / (float)BSZ;
            g_lossTicket = 0u;            // reset for next graph replay
        }
    }
}

// ---------------------------------------------------------------------------
extern "C" void kernel_launch(void* const* d_in, const int* in_sizes, int n_in,
                              void* d_out, int out_size)
{
    const float* img = (const float*)d_in[0];
    const float* txt = (const float*)d_in[1];
    const float* s_I = (const float*)d_in[4];
    const float* s_T = (const float*)d_in[5];
    const int*   iid = (const int*)d_in[6];
    const int*   tid = (const int*)d_in[7];

    static bool attrDone = false;
    if (!attrDone) {
        cudaFuncSetAttribute(k_gemm_fused,
                             cudaFuncAttributeMaxDynamicSharedMemorySize, 2 * STAGEB);
        attrDone = true;
    }

    k_prep<<<BSZ / 8, 256>>>(img, txt);          // warp per row, single pass
    dim3 g(BSZ / BN, BSZ / BM);
    k_gemm_fused<<<g, 256, 2 * STAGEB>>>();
    k_loss<<<NLOSSBLK, 256>>>(s_I, s_T, iid, tid, (float*)d_out);
}